// round 1
// baseline (speedup 1.0000x reference)
#include <cuda_runtime.h>

// Problem constants
#define PB 2
#define PS 2048
#define PD 2048
#define PH 16
#define PHD 128

// Scratch (device globals: allocation-free)
__device__ float g_qkv[(size_t)PB * PS * 3 * PD];   // [B*S, 3D] = 4096 x 6144
__device__ float g_att[(size_t)PB * PS * PD];       // [B*S, D]  = 4096 x 2048

// ---------------------------------------------------------------------------
// SGEMM: C[M,N] = A[M,K] @ B[K,N] + bias[N]
// Block tile 128x128, K-tile 8, 256 threads, 8x8 per-thread.
// Thread col fragments split as [tx*4 .. +3] and [64+tx*4 .. +3] so that
// LDS.128 phases (8 lanes) cover 32 consecutive banks -> conflict-free.
// M,N,K all divide tiles exactly for our shapes; no bounds checks.
// ---------------------------------------------------------------------------
__global__ void __launch_bounds__(256, 2) sgemm_bias(
    const float* __restrict__ A, const float* __restrict__ Bm,
    const float* __restrict__ bias, float* __restrict__ C,
    int M, int N, int K)
{
    __shared__ float As[8][128];   // transposed A tile: As[k][m]
    __shared__ float Bs[8][128];   // Bs[k][n]

    const int tid  = threadIdx.x;
    const int tx   = tid & 15;
    const int ty   = tid >> 4;
    const int row0 = blockIdx.y * 128;
    const int col0 = blockIdx.x * 128;

    const int a_r = tid >> 1;           // 0..127
    const int a_c = (tid & 1) << 2;     // 0 or 4
    const int b_r = tid >> 5;           // 0..7
    const int b_c = (tid & 31) << 2;    // 0..124

    const float* Ap = A  + (size_t)(row0 + a_r) * K + a_c;
    const float* Bp = Bm + (size_t)b_r * N + col0 + b_c;

    float acc[8][8];
    #pragma unroll
    for (int i = 0; i < 8; i++)
        #pragma unroll
        for (int j = 0; j < 8; j++) acc[i][j] = 0.f;

    for (int kt = 0; kt < K; kt += 8) {
        float4 av = *(const float4*)(Ap + kt);
        float4 bv = *(const float4*)(Bp + (size_t)kt * N);
        As[a_c + 0][a_r] = av.x;
        As[a_c + 1][a_r] = av.y;
        As[a_c + 2][a_r] = av.z;
        As[a_c + 3][a_r] = av.w;
        *(float4*)&Bs[b_r][b_c] = bv;
        __syncthreads();

        #pragma unroll
        for (int k = 0; k < 8; k++) {
            float af[8], bf[8];
            #pragma unroll
            for (int i = 0; i < 8; i++) af[i] = As[k][ty * 8 + i];
            #pragma unroll
            for (int j = 0; j < 4; j++) {
                bf[j]     = Bs[k][tx * 4 + j];
                bf[j + 4] = Bs[k][64 + tx * 4 + j];
            }
            #pragma unroll
            for (int i = 0; i < 8; i++)
                #pragma unroll
                for (int j = 0; j < 8; j++)
                    acc[i][j] = fmaf(af[i], bf[j], acc[i][j]);
        }
        __syncthreads();
    }

    #pragma unroll
    for (int i = 0; i < 8; i++) {
        float* Cp = C + (size_t)(row0 + ty * 8 + i) * N;
        const int ca = col0 + tx * 4;
        float4 o0 = make_float4(acc[i][0] + bias[ca + 0],
                                acc[i][1] + bias[ca + 1],
                                acc[i][2] + bias[ca + 2],
                                acc[i][3] + bias[ca + 3]);
        *(float4*)(Cp + ca) = o0;
        const int cb = ca + 64;
        float4 o1 = make_float4(acc[i][4] + bias[cb + 0],
                                acc[i][5] + bias[cb + 1],
                                acc[i][6] + bias[cb + 2],
                                acc[i][7] + bias[cb + 3]);
        *(float4*)(Cp + cb) = o1;
    }
}

// ---------------------------------------------------------------------------
// Flash attention (fp32, online softmax).
// Grid: (S/64, B*H). Block: 256 threads (16x16), each owns a 4-row x 8-col
// slice of the 64x128 O tile (cols split tx*4 / 64+tx*4).
// K stored d-major (KsT[d][key]) so QK^T key-fragments are contiguous.
// Row reductions via shfl_xor within the 16 lanes sharing the same rows.
// ---------------------------------------------------------------------------
#define QSTR 132
#define KSTR 68
#define VSTR 132
#define SSTR 68
#define ATTN_SMEM_FLOATS (64 * QSTR + 128 * KSTR + 64 * VSTR + 64 * SSTR) // 29952

__global__ void __launch_bounds__(256) attn_kernel(
    const float* __restrict__ qkv, float* __restrict__ out)
{
    extern __shared__ float sm[];
    float* Qs  = sm;                       // [64][132]
    float* KsT = Qs + 64 * QSTR;           // [128][68]  (d-major)
    float* Vs  = KsT + 128 * KSTR;         // [64][132]
    float* Ss  = Vs + 64 * VSTR;           // [64][68]   (P tile)

    const int qt = blockIdx.x;             // q tile
    const int bh = blockIdx.y;             // b*H + h
    const int b  = bh >> 4;
    const int h  = bh & 15;
    const int q0 = qt * 64;
    const int tid = threadIdx.x;
    const int tx  = tid & 15;
    const int ty  = tid >> 4;
    const int r0  = ty * 4;
    const int c0  = tx * 4;

    const size_t rs = 3 * PD;              // 6144 row stride in qkv
    const float* qb = qkv + (size_t)b * PS * rs + (size_t)h * PHD;
    const float* kb = qb + PD;
    const float* vb = qb + 2 * PD;

    // Load Q tile (64 x 128)
    #pragma unroll
    for (int i = 0; i < 8; i++) {
        int e  = tid + i * 256;
        int r  = e >> 5;
        int d4 = (e & 31) << 2;
        float4 v = *(const float4*)(qb + (size_t)(q0 + r) * rs + d4);
        *(float4*)&Qs[r * QSTR + d4] = v;
    }

    float m_r[4], l_r[4], o[4][8];
    #pragma unroll
    for (int i = 0; i < 4; i++) {
        m_r[i] = -1e30f;
        l_r[i] = 0.f;
        #pragma unroll
        for (int c = 0; c < 8; c++) o[i][c] = 0.f;
    }
    const float scale = 0.08838834764831845f;  // 1/sqrt(128)

    for (int kt = 0; kt <= qt; kt++) {
        const int k0 = kt * 64;
        __syncthreads();  // previous tile's smem use complete

        // Load K (transposed) and V tiles
        #pragma unroll
        for (int i = 0; i < 8; i++) {
            int e  = tid + i * 256;
            int r  = e >> 5;
            int d4 = (e & 31) << 2;
            float4 kv = *(const float4*)(kb + (size_t)(k0 + r) * rs + d4);
            KsT[(d4 + 0) * KSTR + r] = kv.x;
            KsT[(d4 + 1) * KSTR + r] = kv.y;
            KsT[(d4 + 2) * KSTR + r] = kv.z;
            KsT[(d4 + 3) * KSTR + r] = kv.w;
            float4 vv = *(const float4*)(vb + (size_t)(k0 + r) * rs + d4);
            *(float4*)&Vs[r * VSTR + d4] = vv;
        }
        __syncthreads();

        // S = Q K^T  (4x4 fragment per thread)
        float s[4][4];
        #pragma unroll
        for (int i = 0; i < 4; i++)
            #pragma unroll
            for (int j = 0; j < 4; j++) s[i][j] = 0.f;

        #pragma unroll 4
        for (int d = 0; d < 128; d += 4) {
            float4 aq[4], bk[4];
            #pragma unroll
            for (int i = 0; i < 4; i++)
                aq[i] = *(const float4*)&Qs[(r0 + i) * QSTR + d];
            #pragma unroll
            for (int t = 0; t < 4; t++)
                bk[t] = *(const float4*)&KsT[(d + t) * KSTR + c0];
            #pragma unroll
            for (int i = 0; i < 4; i++) {
                const float a0 = aq[i].x, a1 = aq[i].y, a2 = aq[i].z, a3 = aq[i].w;
                s[i][0] = fmaf(a0, bk[0].x, fmaf(a1, bk[1].x, fmaf(a2, bk[2].x, fmaf(a3, bk[3].x, s[i][0]))));
                s[i][1] = fmaf(a0, bk[0].y, fmaf(a1, bk[1].y, fmaf(a2, bk[2].y, fmaf(a3, bk[3].y, s[i][1]))));
                s[i][2] = fmaf(a0, bk[0].z, fmaf(a1, bk[1].z, fmaf(a2, bk[2].z, fmaf(a3, bk[3].z, s[i][2]))));
                s[i][3] = fmaf(a0, bk[0].w, fmaf(a1, bk[1].w, fmaf(a2, bk[2].w, fmaf(a3, bk[3].w, s[i][3]))));
            }
        }

        // Scale + causal mask (only diagonal tile needs masking)
        #pragma unroll
        for (int i = 0; i < 4; i++)
            #pragma unroll
            for (int j = 0; j < 4; j++) s[i][j] *= scale;
        if (kt == qt) {
            #pragma unroll
            for (int i = 0; i < 4; i++)
                #pragma unroll
                for (int j = 0; j < 4; j++)
                    if (c0 + j > r0 + i) s[i][j] = -1e30f;
        }

        // Row max across 16-lane group
        float mp[4];
        #pragma unroll
        for (int i = 0; i < 4; i++)
            mp[i] = fmaxf(fmaxf(s[i][0], s[i][1]), fmaxf(s[i][2], s[i][3]));
        #pragma unroll
        for (int off = 8; off; off >>= 1)
            #pragma unroll
            for (int i = 0; i < 4; i++)
                mp[i] = fmaxf(mp[i], __shfl_xor_sync(0xffffffffu, mp[i], off));

        float newm[4], alpha[4], sump[4], p[4][4];
        #pragma unroll
        for (int i = 0; i < 4; i++) {
            newm[i]  = fmaxf(m_r[i], mp[i]);
            alpha[i] = __expf(m_r[i] - newm[i]);
            sump[i]  = 0.f;
            #pragma unroll
            for (int j = 0; j < 4; j++) {
                p[i][j] = __expf(s[i][j] - newm[i]);
                sump[i] += p[i][j];
            }
        }
        #pragma unroll
        for (int off = 8; off; off >>= 1)
            #pragma unroll
            for (int i = 0; i < 4; i++)
                sump[i] += __shfl_xor_sync(0xffffffffu, sump[i], off);

        #pragma unroll
        for (int i = 0; i < 4; i++) {
            l_r[i] = l_r[i] * alpha[i] + sump[i];
            m_r[i] = newm[i];
            #pragma unroll
            for (int c = 0; c < 8; c++) o[i][c] *= alpha[i];
            *(float4*)&Ss[(r0 + i) * SSTR + c0] =
                make_float4(p[i][0], p[i][1], p[i][2], p[i][3]);
        }
        __syncthreads();

        // O += P @ V
        #pragma unroll 4
        for (int j = 0; j < 64; j++) {
            float4 v0 = *(const float4*)&Vs[j * VSTR + c0];
            float4 v1 = *(const float4*)&Vs[j * VSTR + 64 + c0];
            #pragma unroll
            for (int i = 0; i < 4; i++) {
                const float pj = Ss[(r0 + i) * SSTR + j];
                o[i][0] = fmaf(pj, v0.x, o[i][0]);
                o[i][1] = fmaf(pj, v0.y, o[i][1]);
                o[i][2] = fmaf(pj, v0.z, o[i][2]);
                o[i][3] = fmaf(pj, v0.w, o[i][3]);
                o[i][4] = fmaf(pj, v1.x, o[i][4]);
                o[i][5] = fmaf(pj, v1.y, o[i][5]);
                o[i][6] = fmaf(pj, v1.z, o[i][6]);
                o[i][7] = fmaf(pj, v1.w, o[i][7]);
            }
        }
    }

    // Normalize and write [B,S,D] with head interleave
    #pragma unroll
    for (int i = 0; i < 4; i++) {
        const float inv = 1.f / l_r[i];
        float* op = out + ((size_t)b * PS + q0 + r0 + i) * PD + h * PHD;
        *(float4*)(op + c0) =
            make_float4(o[i][0] * inv, o[i][1] * inv, o[i][2] * inv, o[i][3] * inv);
        *(float4*)(op + 64 + c0) =
            make_float4(o[i][4] * inv, o[i][5] * inv, o[i][6] * inv, o[i][7] * inv);
    }
}

// ---------------------------------------------------------------------------
extern "C" void kernel_launch(void* const* d_in, const int* in_sizes, int n_in,
                              void* d_out, int out_size)
{
    const float* x     = (const float*)d_in[0];
    const float* w_qkv = (const float*)d_in[1];
    const float* b_qkv = (const float*)d_in[2];
    const float* w_out = (const float*)d_in[3];
    const float* b_out = (const float*)d_in[4];
    float* out = (float*)d_out;

    float* qkv = nullptr;
    float* att = nullptr;
    cudaGetSymbolAddress((void**)&qkv, g_qkv);
    cudaGetSymbolAddress((void**)&att, g_att);

    const int attn_smem = ATTN_SMEM_FLOATS * sizeof(float);  // 119808 B
    cudaFuncSetAttribute(attn_kernel,
                         cudaFuncAttributeMaxDynamicSharedMemorySize, attn_smem);

    dim3 blk(256);
    // QKV projection: [4096,2048] @ [2048,6144]
    sgemm_bias<<<dim3(6144 / 128, 4096 / 128), blk>>>(
        x, w_qkv, b_qkv, qkv, PB * PS, 3 * PD, PD);
    // Causal attention
    attn_kernel<<<dim3(PS / 64, PB * PH), blk, attn_smem>>>(qkv, att);
    // Output projection: [4096,2048] @ [2048,2048]
    sgemm_bias<<<dim3(2048 / 128, 4096 / 128), blk>>>(
        att, w_out, b_out, out, PB * PS, PD, PD);
}

// round 3
// speedup vs baseline: 1.5219x; 1.5219x over previous
#include <cuda_runtime.h>
#include <cuda_bf16.h>
#include <cstdint>

#define PB 2
#define PS 2048
#define PD 2048
#define PH 16
#define PHD 128

// Scratch (device globals: allocation-free)
__device__ float g_qkv[(size_t)PB * PS * 3 * PD];   // [B*S, 3D]
__device__ float g_att[(size_t)PB * PS * PD];       // [B*S, D]

// ============================ helpers ======================================
__device__ __forceinline__ uint32_t smem_u32(const void* p) {
    uint32_t a;
    asm("{ .reg .u64 t; cvta.to.shared.u64 t, %1; cvt.u32.u64 %0, t; }"
        : "=r"(a) : "l"(p));
    return a;
}
__device__ __forceinline__ void ldm_x4(uint32_t* r, uint32_t addr) {
    asm volatile("ldmatrix.sync.aligned.m8n8.x4.shared.b16 {%0,%1,%2,%3}, [%4];"
                 : "=r"(r[0]), "=r"(r[1]), "=r"(r[2]), "=r"(r[3]) : "r"(addr));
}
__device__ __forceinline__ void ldm_x4_t(uint32_t* r, uint32_t addr) {
    asm volatile("ldmatrix.sync.aligned.m8n8.x4.trans.shared.b16 {%0,%1,%2,%3}, [%4];"
                 : "=r"(r[0]), "=r"(r[1]), "=r"(r[2]), "=r"(r[3]) : "r"(addr));
}
__device__ __forceinline__ void mma_bf16(float* d, const uint32_t* a, const uint32_t* b) {
    asm volatile(
        "mma.sync.aligned.m16n8k16.row.col.f32.bf16.bf16.f32 "
        "{%0,%1,%2,%3}, {%4,%5,%6,%7}, {%8,%9}, {%0,%1,%2,%3};"
        : "+f"(d[0]), "+f"(d[1]), "+f"(d[2]), "+f"(d[3])
        : "r"(a[0]), "r"(a[1]), "r"(a[2]), "r"(a[3]), "r"(b[0]), "r"(b[1]));
}
__device__ __forceinline__ uint32_t pack2(__nv_bfloat16 x, __nv_bfloat16 y) {
    uint16_t xr = *reinterpret_cast<uint16_t*>(&x);
    uint16_t yr = *reinterpret_cast<uint16_t*>(&y);
    return (uint32_t)xr | ((uint32_t)yr << 16);
}
// float4 -> (hi uint2, lo uint2) bf16 split
__device__ __forceinline__ void split4(float4 v, uint2& hi, uint2& lo) {
    __nv_bfloat16 h0 = __float2bfloat16(v.x), h1 = __float2bfloat16(v.y);
    __nv_bfloat16 h2 = __float2bfloat16(v.z), h3 = __float2bfloat16(v.w);
    float r0 = v.x - __bfloat162float(h0);
    float r1 = v.y - __bfloat162float(h1);
    float r2 = v.z - __bfloat162float(h2);
    float r3 = v.w - __bfloat162float(h3);
    hi = make_uint2(pack2(h0, h1), pack2(h2, h3));
    lo = make_uint2(pack2(__float2bfloat16(r0), __float2bfloat16(r1)),
                    pack2(__float2bfloat16(r2), __float2bfloat16(r3)));
}

// ===================== bf16x3 mma.sync GEMM ===============================
// C[M,N] = A[M,K]@B[K,N] + bias.  Block 128x128, K-chunk 64, 256 thr,
// double-buffered smem, padded rows (conflict-free ldmatrix), 3-term split.
#define AROW 144
#define BROW 272
#define ATILE (128 * AROW)              // 18432 B  (hi or lo)
#define BTILE (64 * BROW)               // 17408 B
#define STAGE (2 * ATILE + 2 * BTILE)   // 71680 B
#define GK_SMEM (2 * STAGE)             // 143360 B

__global__ void __launch_bounds__(256, 1) gemm_bf16x3(
    const float* __restrict__ A, const float* __restrict__ Bm,
    const float* __restrict__ bias, float* __restrict__ C,
    int M, int N, int K)
{
    extern __shared__ char smc[];
    const uint32_t sb = smem_u32(smc);
    const int tid = threadIdx.x, lane = tid & 31, wid = tid >> 5;
    const int row0 = blockIdx.y * 128, col0 = blockIdx.x * 128;
    const int m0 = (wid & 3) * 32, n0 = (wid >> 2) * 64;
    const int g = lane >> 3, lr = lane & 7;

    float acc[2][8][4];
    #pragma unroll
    for (int i = 0; i < 2; i++)
        #pragma unroll
        for (int j = 0; j < 8; j++)
            #pragma unroll
            for (int q = 0; q < 4; q++) acc[i][j][q] = 0.f;

    float4 stg[8];  // staging regs (A or B half of a chunk)

    auto LOAD_A = [&](int kc) {
        #pragma unroll
        for (int it = 0; it < 8; it++) {
            int e = tid + it * 256;
            stg[it] = *(const float4*)(A + (size_t)(row0 + (e >> 4)) * K + kc + ((e & 15) << 2));
        }
    };
    auto LOAD_B = [&](int kc) {
        #pragma unroll
        for (int it = 0; it < 8; it++) {
            int e = tid + it * 256;
            stg[it] = *(const float4*)(Bm + (size_t)(kc + (e >> 5)) * N + col0 + ((e & 31) << 2));
        }
    };
    auto STORE_A = [&](char* st) {
        char* Ahi = st;
        char* Alo = st + ATILE;
        #pragma unroll
        for (int it = 0; it < 8; it++) {
            int e = tid + it * 256;
            int m = e >> 4, ks = (e & 15) << 2;
            uint2 hi, lo;
            split4(stg[it], hi, lo);
            *(uint2*)(Ahi + m * AROW + ks * 2) = hi;
            *(uint2*)(Alo + m * AROW + ks * 2) = lo;
        }
    };
    auto STORE_B = [&](char* st) {
        char* Bhi = st + 2 * ATILE;
        char* Blo = st + 2 * ATILE + BTILE;
        #pragma unroll
        for (int it = 0; it < 8; it++) {
            int e = tid + it * 256;
            int k = e >> 5, ns = (e & 31) << 2;
            uint2 hi, lo;
            split4(stg[it], hi, lo);
            *(uint2*)(Bhi + k * BROW + ns * 2) = hi;
            *(uint2*)(Blo + k * BROW + ns * 2) = lo;
        }
    };

    // two k-steps (ks0, ks0+1) of the 4 in a chunk
    auto MMA2 = [&](uint32_t staddr, int ks0) {
        const uint32_t Ahi = staddr;
        const uint32_t Bhi = staddr + 2 * ATILE;
        #pragma unroll
        for (int ks = ks0; ks < ks0 + 2; ks++) {
            const int kb = ks * 16;
            uint32_t aH[2][4], aL[2][4], bH[8][2], bL[8][2];
            #pragma unroll
            for (int mt = 0; mt < 2; mt++) {
                int r = m0 + mt * 16 + lr + ((g & 1) << 3);
                uint32_t ad = Ahi + r * AROW + (kb + ((g >> 1) << 3)) * 2;
                ldm_x4(aH[mt], ad);
                ldm_x4(aL[mt], ad + ATILE);
            }
            #pragma unroll
            for (int q = 0; q < 4; q++) {
                int kk = kb + lr + ((g & 1) << 3);
                uint32_t bd = Bhi + kk * BROW + (n0 + q * 16 + ((g >> 1) << 3)) * 2;
                uint32_t t[4];
                ldm_x4_t(t, bd);
                bH[2 * q][0] = t[0]; bH[2 * q][1] = t[1];
                bH[2 * q + 1][0] = t[2]; bH[2 * q + 1][1] = t[3];
                ldm_x4_t(t, bd + BTILE);
                bL[2 * q][0] = t[0]; bL[2 * q][1] = t[1];
                bL[2 * q + 1][0] = t[2]; bL[2 * q + 1][1] = t[3];
            }
            #pragma unroll
            for (int mt = 0; mt < 2; mt++)
                #pragma unroll
                for (int nt = 0; nt < 8; nt++) {
                    mma_bf16(acc[mt][nt], aH[mt], bH[nt]);
                    mma_bf16(acc[mt][nt], aH[mt], bL[nt]);
                    mma_bf16(acc[mt][nt], aL[mt], bH[nt]);
                }
        }
    };

    const int NCH = K >> 6;

    LOAD_A(0); STORE_A(smc);
    LOAD_B(0); STORE_B(smc);
    __syncthreads();

    for (int c = 0; c < NCH; c++) {
        char* nxt = smc + ((c + 1) & 1) * STAGE;
        const uint32_t cur = sb + (uint32_t)(c & 1) * STAGE;
        const bool more = (c + 1 < NCH);
        const int kcn = (c + 1) << 6;
        if (more) LOAD_A(kcn);
        MMA2(cur, 0);
        if (more) { STORE_A(nxt); LOAD_B(kcn); }
        MMA2(cur, 2);
        if (more) STORE_B(nxt);
        __syncthreads();
    }

    // epilogue: direct STG.64 with bias
    #pragma unroll
    for (int mt = 0; mt < 2; mt++) {
        #pragma unroll
        for (int nt = 0; nt < 8; nt++) {
            const int r = row0 + m0 + mt * 16 + (lane >> 2);
            const int cc = col0 + n0 + nt * 8 + ((lane & 3) << 1);
            const float b0 = bias[cc], b1 = bias[cc + 1];
            *(float2*)(C + (size_t)r * N + cc) =
                make_float2(acc[mt][nt][0] + b0, acc[mt][nt][1] + b1);
            *(float2*)(C + (size_t)(r + 8) * N + cc) =
                make_float2(acc[mt][nt][2] + b0, acc[mt][nt][3] + b1);
        }
    }
}

// ======================= Flash attention (fp32 SIMT) =======================
#define QSTR 132
#define KSTR 68
#define VSTR 132
#define SSTR 68
#define ATTN_SMEM_FLOATS (64 * QSTR + 128 * KSTR + 64 * VSTR + 64 * SSTR)

__global__ void __launch_bounds__(256) attn_kernel(
    const float* __restrict__ qkv, float* __restrict__ out)
{
    extern __shared__ float sm[];
    float* Qs  = sm;
    float* KsT = Qs + 64 * QSTR;
    float* Vs  = KsT + 128 * KSTR;
    float* Ss  = Vs + 64 * VSTR;

    const int qt = blockIdx.x;
    const int bh = blockIdx.y;
    const int b  = bh >> 4;
    const int h  = bh & 15;
    const int q0 = qt * 64;
    const int tid = threadIdx.x;
    const int tx  = tid & 15;
    const int ty  = tid >> 4;
    const int r0  = ty * 4;
    const int c0  = tx * 4;

    const size_t rs = 3 * PD;
    const float* qb = qkv + (size_t)b * PS * rs + (size_t)h * PHD;
    const float* kb = qb + PD;
    const float* vb = qb + 2 * PD;

    #pragma unroll
    for (int i = 0; i < 8; i++) {
        int e  = tid + i * 256;
        int r  = e >> 5;
        int d4 = (e & 31) << 2;
        float4 v = *(const float4*)(qb + (size_t)(q0 + r) * rs + d4);
        *(float4*)&Qs[r * QSTR + d4] = v;
    }

    float m_r[4], l_r[4], o[4][8];
    #pragma unroll
    for (int i = 0; i < 4; i++) {
        m_r[i] = -1e30f;
        l_r[i] = 0.f;
        #pragma unroll
        for (int c = 0; c < 8; c++) o[i][c] = 0.f;
    }
    const float scale = 0.08838834764831845f;

    for (int kt = 0; kt <= qt; kt++) {
        const int k0 = kt * 64;
        __syncthreads();

        #pragma unroll
        for (int i = 0; i < 8; i++) {
            int e  = tid + i * 256;
            int r  = e >> 5;
            int d4 = (e & 31) << 2;
            float4 kv = *(const float4*)(kb + (size_t)(k0 + r) * rs + d4);
            KsT[(d4 + 0) * KSTR + r] = kv.x;
            KsT[(d4 + 1) * KSTR + r] = kv.y;
            KsT[(d4 + 2) * KSTR + r] = kv.z;
            KsT[(d4 + 3) * KSTR + r] = kv.w;
            float4 vv = *(const float4*)(vb + (size_t)(k0 + r) * rs + d4);
            *(float4*)&Vs[r * VSTR + d4] = vv;
        }
        __syncthreads();

        float s[4][4];
        #pragma unroll
        for (int i = 0; i < 4; i++)
            #pragma unroll
            for (int j = 0; j < 4; j++) s[i][j] = 0.f;

        #pragma unroll 4
        for (int d = 0; d < 128; d += 4) {
            float4 aq[4], bk[4];
            #pragma unroll
            for (int i = 0; i < 4; i++)
                aq[i] = *(const float4*)&Qs[(r0 + i) * QSTR + d];
            #pragma unroll
            for (int t = 0; t < 4; t++)
                bk[t] = *(const float4*)&KsT[(d + t) * KSTR + c0];
            #pragma unroll
            for (int i = 0; i < 4; i++) {
                const float a0 = aq[i].x, a1 = aq[i].y, a2 = aq[i].z, a3 = aq[i].w;
                s[i][0] = fmaf(a0, bk[0].x, fmaf(a1, bk[1].x, fmaf(a2, bk[2].x, fmaf(a3, bk[3].x, s[i][0]))));
                s[i][1] = fmaf(a0, bk[0].y, fmaf(a1, bk[1].y, fmaf(a2, bk[2].y, fmaf(a3, bk[3].y, s[i][1]))));
                s[i][2] = fmaf(a0, bk[0].z, fmaf(a1, bk[1].z, fmaf(a2, bk[2].z, fmaf(a3, bk[3].z, s[i][2]))));
                s[i][3] = fmaf(a0, bk[0].w, fmaf(a1, bk[1].w, fmaf(a2, bk[2].w, fmaf(a3, bk[3].w, s[i][3]))));
            }
        }

        #pragma unroll
        for (int i = 0; i < 4; i++)
            #pragma unroll
            for (int j = 0; j < 4; j++) s[i][j] *= scale;
        if (kt == qt) {
            #pragma unroll
            for (int i = 0; i < 4; i++)
                #pragma unroll
                for (int j = 0; j < 4; j++)
                    if (c0 + j > r0 + i) s[i][j] = -1e30f;
        }

        float mp[4];
        #pragma unroll
        for (int i = 0; i < 4; i++)
            mp[i] = fmaxf(fmaxf(s[i][0], s[i][1]), fmaxf(s[i][2], s[i][3]));
        #pragma unroll
        for (int off = 8; off; off >>= 1)
            #pragma unroll
            for (int i = 0; i < 4; i++)
                mp[i] = fmaxf(mp[i], __shfl_xor_sync(0xffffffffu, mp[i], off));

        float newm[4], alpha[4], sump[4], p[4][4];
        #pragma unroll
        for (int i = 0; i < 4; i++) {
            newm[i]  = fmaxf(m_r[i], mp[i]);
            alpha[i] = __expf(m_r[i] - newm[i]);
            sump[i]  = 0.f;
            #pragma unroll
            for (int j = 0; j < 4; j++) {
                p[i][j] = __expf(s[i][j] - newm[i]);
                sump[i] += p[i][j];
            }
        }
        #pragma unroll
        for (int off = 8; off; off >>= 1)
            #pragma unroll
            for (int i = 0; i < 4; i++)
                sump[i] += __shfl_xor_sync(0xffffffffu, sump[i], off);

        #pragma unroll
        for (int i = 0; i < 4; i++) {
            l_r[i] = l_r[i] * alpha[i] + sump[i];
            m_r[i] = newm[i];
            #pragma unroll
            for (int c = 0; c < 8; c++) o[i][c] *= alpha[i];
            *(float4*)&Ss[(r0 + i) * SSTR + c0] =
                make_float4(p[i][0], p[i][1], p[i][2], p[i][3]);
        }
        __syncthreads();

        #pragma unroll 4
        for (int j = 0; j < 64; j++) {
            float4 v0 = *(const float4*)&Vs[j * VSTR + c0];
            float4 v1 = *(const float4*)&Vs[j * VSTR + 64 + c0];
            #pragma unroll
            for (int i = 0; i < 4; i++) {
                const float pj = Ss[(r0 + i) * SSTR + j];
                o[i][0] = fmaf(pj, v0.x, o[i][0]);
                o[i][1] = fmaf(pj, v0.y, o[i][1]);
                o[i][2] = fmaf(pj, v0.z, o[i][2]);
                o[i][3] = fmaf(pj, v0.w, o[i][3]);
                o[i][4] = fmaf(pj, v1.x, o[i][4]);
                o[i][5] = fmaf(pj, v1.y, o[i][5]);
                o[i][6] = fmaf(pj, v1.z, o[i][6]);
                o[i][7] = fmaf(pj, v1.w, o[i][7]);
            }
        }
    }

    #pragma unroll
    for (int i = 0; i < 4; i++) {
        const float inv = 1.f / l_r[i];
        float* op = out + ((size_t)b * PS + q0 + r0 + i) * PD + h * PHD;
        *(float4*)(op + c0) =
            make_float4(o[i][0] * inv, o[i][1] * inv, o[i][2] * inv, o[i][3] * inv);
        *(float4*)(op + 64 + c0) =
            make_float4(o[i][4] * inv, o[i][5] * inv, o[i][6] * inv, o[i][7] * inv);
    }
}

// ---------------------------------------------------------------------------
extern "C" void kernel_launch(void* const* d_in, const int* in_sizes, int n_in,
                              void* d_out, int out_size)
{
    const float* x     = (const float*)d_in[0];
    const float* w_qkv = (const float*)d_in[1];
    const float* b_qkv = (const float*)d_in[2];
    const float* w_out = (const float*)d_in[3];
    const float* b_out = (const float*)d_in[4];
    float* out = (float*)d_out;

    float* qkv = nullptr;
    float* att = nullptr;
    cudaGetSymbolAddress((void**)&qkv, g_qkv);
    cudaGetSymbolAddress((void**)&att, g_att);

    const int attn_smem = ATTN_SMEM_FLOATS * sizeof(float);
    cudaFuncSetAttribute(attn_kernel,
                         cudaFuncAttributeMaxDynamicSharedMemorySize, attn_smem);
    cudaFuncSetAttribute(gemm_bf16x3,
                         cudaFuncAttributeMaxDynamicSharedMemorySize, GK_SMEM);

    // QKV projection: [4096,2048] @ [2048,6144]
    gemm_bf16x3<<<dim3(6144 / 128, 4096 / 128), 256, GK_SMEM>>>(
        x, w_qkv, b_qkv, qkv, PB * PS, 3 * PD, PD);
    // Causal attention
    attn_kernel<<<dim3(PS / 64, PB * PH), 256, attn_smem>>>(qkv, att);
    // Output projection: [4096,2048] @ [2048,2048]
    gemm_bf16x3<<<dim3(2048 / 128, 4096 / 128), 256, GK_SMEM>>>(
        att, w_out, b_out, out, PB * PS, PD, PD);
}

// round 4
// speedup vs baseline: 2.1639x; 1.4218x over previous
#include <cuda_runtime.h>
#include <cuda_bf16.h>
#include <cstdint>

#define PB 2
#define PS 2048
#define PD 2048
#define PH 16
#define PHD 128

// Scratch (device globals: allocation-free)
__device__ float g_qkv[(size_t)PB * PS * 3 * PD];   // [B*S, 3D]
__device__ float g_att[(size_t)PB * PS * PD];       // [B*S, D]

// ============================ helpers ======================================
__device__ __forceinline__ uint32_t smem_u32(const void* p) {
    uint32_t a;
    asm("{ .reg .u64 t; cvta.to.shared.u64 t, %1; cvt.u32.u64 %0, t; }"
        : "=r"(a) : "l"(p));
    return a;
}
__device__ __forceinline__ void ldm_x4(uint32_t* r, uint32_t addr) {
    asm volatile("ldmatrix.sync.aligned.m8n8.x4.shared.b16 {%0,%1,%2,%3}, [%4];"
                 : "=r"(r[0]), "=r"(r[1]), "=r"(r[2]), "=r"(r[3]) : "r"(addr));
}
__device__ __forceinline__ void ldm_x4_t(uint32_t* r, uint32_t addr) {
    asm volatile("ldmatrix.sync.aligned.m8n8.x4.trans.shared.b16 {%0,%1,%2,%3}, [%4];"
                 : "=r"(r[0]), "=r"(r[1]), "=r"(r[2]), "=r"(r[3]) : "r"(addr));
}
__device__ __forceinline__ void mma_bf16(float* d, const uint32_t* a, const uint32_t* b) {
    asm volatile(
        "mma.sync.aligned.m16n8k16.row.col.f32.bf16.bf16.f32 "
        "{%0,%1,%2,%3}, {%4,%5,%6,%7}, {%8,%9}, {%0,%1,%2,%3};"
        : "+f"(d[0]), "+f"(d[1]), "+f"(d[2]), "+f"(d[3])
        : "r"(a[0]), "r"(a[1]), "r"(a[2]), "r"(a[3]), "r"(b[0]), "r"(b[1]));
}
__device__ __forceinline__ uint32_t pack2(__nv_bfloat16 x, __nv_bfloat16 y) {
    uint16_t xr = *reinterpret_cast<uint16_t*>(&x);
    uint16_t yr = *reinterpret_cast<uint16_t*>(&y);
    return (uint32_t)xr | ((uint32_t)yr << 16);
}
// float4 -> (hi uint2, lo uint2) bf16 split
__device__ __forceinline__ void split4(float4 v, uint2& hi, uint2& lo) {
    __nv_bfloat16 h0 = __float2bfloat16(v.x), h1 = __float2bfloat16(v.y);
    __nv_bfloat16 h2 = __float2bfloat16(v.z), h3 = __float2bfloat16(v.w);
    float r0 = v.x - __bfloat162float(h0);
    float r1 = v.y - __bfloat162float(h1);
    float r2 = v.z - __bfloat162float(h2);
    float r3 = v.w - __bfloat162float(h3);
    hi = make_uint2(pack2(h0, h1), pack2(h2, h3));
    lo = make_uint2(pack2(__float2bfloat16(r0), __float2bfloat16(r1)),
                    pack2(__float2bfloat16(r2), __float2bfloat16(r3)));
}
// pack two floats' bf16-hi and bf16-lo parts
__device__ __forceinline__ void packhl(float x, float y, uint32_t& hi, uint32_t& lo) {
    __nv_bfloat16 hx = __float2bfloat16(x), hy = __float2bfloat16(y);
    hi = pack2(hx, hy);
    lo = pack2(__float2bfloat16(x - __bfloat162float(hx)),
               __float2bfloat16(y - __bfloat162float(hy)));
}

// ===================== bf16x3 mma.sync GEMM ===============================
#define AROW 144
#define BROW 272
#define ATILE (128 * AROW)
#define BTILE (64 * BROW)
#define STAGE (2 * ATILE + 2 * BTILE)
#define GK_SMEM (2 * STAGE)

__global__ void __launch_bounds__(256, 1) gemm_bf16x3(
    const float* __restrict__ A, const float* __restrict__ Bm,
    const float* __restrict__ bias, float* __restrict__ C,
    int M, int N, int K)
{
    extern __shared__ char smc[];
    const uint32_t sb = smem_u32(smc);
    const int tid = threadIdx.x, lane = tid & 31, wid = tid >> 5;
    const int row0 = blockIdx.y * 128, col0 = blockIdx.x * 128;
    const int m0 = (wid & 3) * 32, n0 = (wid >> 2) * 64;
    const int g = lane >> 3, lr = lane & 7;

    float acc[2][8][4];
    #pragma unroll
    for (int i = 0; i < 2; i++)
        #pragma unroll
        for (int j = 0; j < 8; j++)
            #pragma unroll
            for (int q = 0; q < 4; q++) acc[i][j][q] = 0.f;

    float4 stg[8];

    auto LOAD_A = [&](int kc) {
        #pragma unroll
        for (int it = 0; it < 8; it++) {
            int e = tid + it * 256;
            stg[it] = *(const float4*)(A + (size_t)(row0 + (e >> 4)) * K + kc + ((e & 15) << 2));
        }
    };
    auto LOAD_B = [&](int kc) {
        #pragma unroll
        for (int it = 0; it < 8; it++) {
            int e = tid + it * 256;
            stg[it] = *(const float4*)(Bm + (size_t)(kc + (e >> 5)) * N + col0 + ((e & 31) << 2));
        }
    };
    auto STORE_A = [&](char* st) {
        char* Ahi = st;
        char* Alo = st + ATILE;
        #pragma unroll
        for (int it = 0; it < 8; it++) {
            int e = tid + it * 256;
            int m = e >> 4, ks = (e & 15) << 2;
            uint2 hi, lo;
            split4(stg[it], hi, lo);
            *(uint2*)(Ahi + m * AROW + ks * 2) = hi;
            *(uint2*)(Alo + m * AROW + ks * 2) = lo;
        }
    };
    auto STORE_B = [&](char* st) {
        char* Bhi = st + 2 * ATILE;
        char* Blo = st + 2 * ATILE + BTILE;
        #pragma unroll
        for (int it = 0; it < 8; it++) {
            int e = tid + it * 256;
            int k = e >> 5, ns = (e & 31) << 2;
            uint2 hi, lo;
            split4(stg[it], hi, lo);
            *(uint2*)(Bhi + k * BROW + ns * 2) = hi;
            *(uint2*)(Blo + k * BROW + ns * 2) = lo;
        }
    };

    auto MMA2 = [&](uint32_t staddr, int ks0) {
        const uint32_t Ahi = staddr;
        const uint32_t Bhi = staddr + 2 * ATILE;
        #pragma unroll
        for (int ks = ks0; ks < ks0 + 2; ks++) {
            const int kb = ks * 16;
            uint32_t aH[2][4], aL[2][4], bH[8][2], bL[8][2];
            #pragma unroll
            for (int mt = 0; mt < 2; mt++) {
                int r = m0 + mt * 16 + lr + ((g & 1) << 3);
                uint32_t ad = Ahi + r * AROW + (kb + ((g >> 1) << 3)) * 2;
                ldm_x4(aH[mt], ad);
                ldm_x4(aL[mt], ad + ATILE);
            }
            #pragma unroll
            for (int q = 0; q < 4; q++) {
                int kk = kb + lr + ((g & 1) << 3);
                uint32_t bd = Bhi + kk * BROW + (n0 + q * 16 + ((g >> 1) << 3)) * 2;
                uint32_t t[4];
                ldm_x4_t(t, bd);
                bH[2 * q][0] = t[0]; bH[2 * q][1] = t[1];
                bH[2 * q + 1][0] = t[2]; bH[2 * q + 1][1] = t[3];
                ldm_x4_t(t, bd + BTILE);
                bL[2 * q][0] = t[0]; bL[2 * q][1] = t[1];
                bL[2 * q + 1][0] = t[2]; bL[2 * q + 1][1] = t[3];
            }
            #pragma unroll
            for (int mt = 0; mt < 2; mt++)
                #pragma unroll
                for (int nt = 0; nt < 8; nt++) {
                    mma_bf16(acc[mt][nt], aH[mt], bH[nt]);
                    mma_bf16(acc[mt][nt], aH[mt], bL[nt]);
                    mma_bf16(acc[mt][nt], aL[mt], bH[nt]);
                }
        }
    };

    const int NCH = K >> 6;

    LOAD_A(0); STORE_A(smc);
    LOAD_B(0); STORE_B(smc);
    __syncthreads();

    for (int c = 0; c < NCH; c++) {
        char* nxt = smc + ((c + 1) & 1) * STAGE;
        const uint32_t cur = sb + (uint32_t)(c & 1) * STAGE;
        const bool more = (c + 1 < NCH);
        const int kcn = (c + 1) << 6;
        if (more) LOAD_A(kcn);
        MMA2(cur, 0);
        if (more) { STORE_A(nxt); LOAD_B(kcn); }
        MMA2(cur, 2);
        if (more) STORE_B(nxt);
        __syncthreads();
    }

    #pragma unroll
    for (int mt = 0; mt < 2; mt++) {
        #pragma unroll
        for (int nt = 0; nt < 8; nt++) {
            const int r = row0 + m0 + mt * 16 + (lane >> 2);
            const int cc = col0 + n0 + nt * 8 + ((lane & 3) << 1);
            const float b0 = bias[cc], b1 = bias[cc + 1];
            *(float2*)(C + (size_t)r * N + cc) =
                make_float2(acc[mt][nt][0] + b0, acc[mt][nt][1] + b1);
            *(float2*)(C + (size_t)(r + 8) * N + cc) =
                make_float2(acc[mt][nt][2] + b0, acc[mt][nt][3] + b1);
        }
    }
}

// ================== Flash attention, bf16x3 mma.sync ======================
// Block: 128 q-rows x (b,h). 8 warps x 16 rows. kv tiles of 64.
// Q/K/V split hi/lo bf16 in smem, 272B padded rows (conflict-free ldmatrix).
// S and O live in mma fragment registers; softmax in fragment layout.
#define BQ 128
#define BK 64
#define TROW 272                       // 128 bf16 + 8 pad, bytes
#define QTILE (128 * TROW)             // 34816
#define KTILE (64 * TROW)              // 17408
#define AT_SMEM (2 * QTILE + 4 * KTILE)  // 139264

__global__ void __launch_bounds__(256, 1) attn_mma(
    const float* __restrict__ qkv, float* __restrict__ out)
{
    extern __shared__ char smc[];
    const uint32_t sb = smem_u32(smc);
    char* cQhi = smc;
    char* cQlo = smc + QTILE;
    char* cKhi = smc + 2 * QTILE;
    char* cKlo = cKhi + KTILE;
    char* cVhi = cKlo + KTILE;
    char* cVlo = cVhi + KTILE;
    const uint32_t sQhi = sb;
    const uint32_t sKhi = sb + 2 * QTILE;
    const uint32_t sVhi = sKhi + 2 * KTILE;

    const int qt = (int)gridDim.x - 1 - (int)blockIdx.x;  // heavy blocks first
    const int bh = blockIdx.y;
    const int b  = bh >> 4;
    const int h  = bh & 15;
    const int q0 = qt * BQ;
    const int tid  = threadIdx.x;
    const int lane = tid & 31;
    const int wid  = tid >> 5;
    const int lr   = lane & 7;
    const int g    = lane >> 3;
    const int rl   = lane >> 2;            // row within 16-row half
    const int cq   = (lane & 3) << 1;      // col pair base

    const size_t rs = 3 * PD;
    const float* qb = qkv + (size_t)b * PS * rs + (size_t)h * PHD;
    const float* kb = qb + PD;
    const float* vb = qb + 2 * PD;

    // Load + split Q tile (128 x 128)
    #pragma unroll
    for (int it = 0; it < 16; it++) {
        int e = tid + it * 256;
        int r = e >> 5, c4 = (e & 31) << 2;
        float4 v = *(const float4*)(qb + (size_t)(q0 + r) * rs + c4);
        uint2 hi, lo;
        split4(v, hi, lo);
        *(uint2*)(cQhi + r * TROW + c4 * 2) = hi;
        *(uint2*)(cQlo + r * TROW + c4 * 2) = lo;
    }

    float O[16][4];
    #pragma unroll
    for (int nt = 0; nt < 16; nt++)
        #pragma unroll
        for (int c = 0; c < 4; c++) O[nt][c] = 0.f;
    float m0r = -1e30f, m1r = -1e30f, l0r = 0.f, l1r = 0.f;
    const float scale = 0.08838834764831845f;
    const int row_g0 = q0 + wid * 16 + rl;   // global q row (half 0)
    const int row_g1 = row_g0 + 8;

    const int nkt = 2 * qt + 2;
    for (int kt = 0; kt < nkt; kt++) {
        const int k0 = kt * BK;
        __syncthreads();
        // Load + split K, V tiles (64 x 128)
        #pragma unroll
        for (int it = 0; it < 8; it++) {
            int e = tid + it * 256;
            int r = e >> 5, c4 = (e & 31) << 2;
            uint2 hi, lo;
            float4 kv = *(const float4*)(kb + (size_t)(k0 + r) * rs + c4);
            split4(kv, hi, lo);
            *(uint2*)(cKhi + r * TROW + c4 * 2) = hi;
            *(uint2*)(cKlo + r * TROW + c4 * 2) = lo;
            float4 vv = *(const float4*)(vb + (size_t)(k0 + r) * rs + c4);
            split4(vv, hi, lo);
            *(uint2*)(cVhi + r * TROW + c4 * 2) = hi;
            *(uint2*)(cVlo + r * TROW + c4 * 2) = lo;
        }
        __syncthreads();

        // ---- S = Q K^T (3-term bf16)
        float S[8][4];
        #pragma unroll
        for (int j = 0; j < 8; j++)
            #pragma unroll
            for (int c = 0; c < 4; c++) S[j][c] = 0.f;

        #pragma unroll
        for (int ks = 0; ks < 8; ks++) {
            uint32_t aH[4], aL[4];
            const uint32_t ad = sQhi + (wid * 16 + lr + ((g & 1) << 3)) * TROW
                                     + (ks * 16 + ((g >> 1) << 3)) * 2;
            ldm_x4(aH, ad);
            ldm_x4(aL, ad + QTILE);
            #pragma unroll
            for (int p = 0; p < 4; p++) {
                uint32_t kH[4], kL[4];
                const uint32_t kd = sKhi + (p * 16 + lr + ((g >> 1) << 3)) * TROW
                                         + (ks * 16 + ((g & 1) << 3)) * 2;
                ldm_x4(kH, kd);            // non-trans: K stored [key][d] == .col B
                ldm_x4(kL, kd + KTILE);
                mma_bf16(S[2 * p],     aH, kH);
                mma_bf16(S[2 * p],     aH, kL);
                mma_bf16(S[2 * p],     aL, kH);
                mma_bf16(S[2 * p + 1], aH, kH + 2);
                mma_bf16(S[2 * p + 1], aH, kL + 2);
                mma_bf16(S[2 * p + 1], aL, kH + 2);
            }
        }

        // ---- scale + causal mask
        const bool need_mask = (k0 + BK - 1 > q0);
        float mx0 = -1e30f, mx1 = -1e30f;
        #pragma unroll
        for (int j = 0; j < 8; j++) {
            #pragma unroll
            for (int c = 0; c < 4; c++) {
                float s = S[j][c] * scale;
                if (need_mask) {
                    const int col = k0 + j * 8 + cq + (c & 1);
                    const int row = (c < 2) ? row_g0 : row_g1;
                    if (col > row) s = -1e30f;
                }
                S[j][c] = s;
            }
            mx0 = fmaxf(mx0, fmaxf(S[j][0], S[j][1]));
            mx1 = fmaxf(mx1, fmaxf(S[j][2], S[j][3]));
        }
        #pragma unroll
        for (int off = 1; off <= 2; off <<= 1) {
            mx0 = fmaxf(mx0, __shfl_xor_sync(0xffffffffu, mx0, off));
            mx1 = fmaxf(mx1, __shfl_xor_sync(0xffffffffu, mx1, off));
        }
        const float nm0 = fmaxf(m0r, mx0), nm1 = fmaxf(m1r, mx1);
        const float al0 = __expf(m0r - nm0), al1 = __expf(m1r - nm1);
        float sum0 = 0.f, sum1 = 0.f;
        #pragma unroll
        for (int j = 0; j < 8; j++) {
            S[j][0] = __expf(S[j][0] - nm0);
            S[j][1] = __expf(S[j][1] - nm0);
            S[j][2] = __expf(S[j][2] - nm1);
            S[j][3] = __expf(S[j][3] - nm1);
            sum0 += S[j][0] + S[j][1];
            sum1 += S[j][2] + S[j][3];
        }
        #pragma unroll
        for (int off = 1; off <= 2; off <<= 1) {
            sum0 += __shfl_xor_sync(0xffffffffu, sum0, off);
            sum1 += __shfl_xor_sync(0xffffffffu, sum1, off);
        }
        l0r = l0r * al0 + sum0;
        l1r = l1r * al1 + sum1;
        m0r = nm0; m1r = nm1;
        #pragma unroll
        for (int nt = 0; nt < 16; nt++) {
            O[nt][0] *= al0; O[nt][1] *= al0;
            O[nt][2] *= al1; O[nt][3] *= al1;
        }

        // ---- O += P V (3-term bf16), P repacked from S fragments
        #pragma unroll
        for (int kk = 0; kk < 4; kk++) {
            uint32_t aPh[4], aPl[4];
            const int j0 = 2 * kk, j1 = 2 * kk + 1;
            packhl(S[j0][0], S[j0][1], aPh[0], aPl[0]);
            packhl(S[j0][2], S[j0][3], aPh[1], aPl[1]);
            packhl(S[j1][0], S[j1][1], aPh[2], aPl[2]);
            packhl(S[j1][2], S[j1][3], aPh[3], aPl[3]);
            #pragma unroll
            for (int np = 0; np < 8; np++) {
                uint32_t vH[4], vL[4];
                const uint32_t vd = sVhi + (kk * 16 + lr + ((g & 1) << 3)) * TROW
                                         + (np * 16 + ((g >> 1) << 3)) * 2;
                ldm_x4_t(vH, vd);          // V stored [key][d] == [k][n]
                ldm_x4_t(vL, vd + KTILE);
                mma_bf16(O[2 * np],     aPh, vH);
                mma_bf16(O[2 * np],     aPh, vL);
                mma_bf16(O[2 * np],     aPl, vH);
                mma_bf16(O[2 * np + 1], aPh, vH + 2);
                mma_bf16(O[2 * np + 1], aPh, vL + 2);
                mma_bf16(O[2 * np + 1], aPl, vH + 2);
            }
        }
    }

    // ---- normalize + write [B,S,D] with head offset
    const float inv0 = 1.f / l0r, inv1 = 1.f / l1r;
    float* op0 = out + ((size_t)b * PS + row_g0) * PD + h * PHD;
    float* op1 = out + ((size_t)b * PS + row_g1) * PD + h * PHD;
    #pragma unroll
    for (int nt = 0; nt < 16; nt++) {
        const int col = nt * 8 + cq;
        *(float2*)(op0 + col) = make_float2(O[nt][0] * inv0, O[nt][1] * inv0);
        *(float2*)(op1 + col) = make_float2(O[nt][2] * inv1, O[nt][3] * inv1);
    }
}

// ---------------------------------------------------------------------------
extern "C" void kernel_launch(void* const* d_in, const int* in_sizes, int n_in,
                              void* d_out, int out_size)
{
    const float* x     = (const float*)d_in[0];
    const float* w_qkv = (const float*)d_in[1];
    const float* b_qkv = (const float*)d_in[2];
    const float* w_out = (const float*)d_in[3];
    const float* b_out = (const float*)d_in[4];
    float* out = (float*)d_out;

    float* qkv = nullptr;
    float* att = nullptr;
    cudaGetSymbolAddress((void**)&qkv, g_qkv);
    cudaGetSymbolAddress((void**)&att, g_att);

    cudaFuncSetAttribute(gemm_bf16x3,
                         cudaFuncAttributeMaxDynamicSharedMemorySize, GK_SMEM);
    cudaFuncSetAttribute(attn_mma,
                         cudaFuncAttributeMaxDynamicSharedMemorySize, AT_SMEM);

    // QKV projection: [4096,2048] @ [2048,6144]
    gemm_bf16x3<<<dim3(6144 / 128, 4096 / 128), 256, GK_SMEM>>>(
        x, w_qkv, b_qkv, qkv, PB * PS, 3 * PD, PD);
    // Causal attention (tensor-core)
    attn_mma<<<dim3(PS / BQ, PB * PH), 256, AT_SMEM>>>(qkv, att);
    // Output projection: [4096,2048] @ [2048,2048]
    gemm_bf16x3<<<dim3(2048 / 128, 4096 / 128), 256, GK_SMEM>>>(
        att, w_out, b_out, out, PB * PS, PD, PD);
}

// round 5
// speedup vs baseline: 2.5023x; 1.1564x over previous
#include <cuda_runtime.h>
#include <cuda_bf16.h>
#include <cstdint>

#define PB 2
#define PS 2048
#define PD 2048
#define PH 16
#define PHD 128

typedef unsigned short u16;

// Scratch (device globals: allocation-free), bf16 raw
__device__ u16 g_x_hi[(size_t)PB * PS * PD];
__device__ u16 g_x_lo[(size_t)PB * PS * PD];
__device__ u16 g_wqkv_hi[(size_t)PD * 3 * PD];
__device__ u16 g_wqkv_lo[(size_t)PD * 3 * PD];
__device__ u16 g_wout_hi[(size_t)PD * PD];
__device__ u16 g_wout_lo[(size_t)PD * PD];
__device__ u16 g_qkv_hi[(size_t)PB * PS * 3 * PD];
__device__ u16 g_qkv_lo[(size_t)PB * PS * 3 * PD];
__device__ u16 g_att_hi[(size_t)PB * PS * PD];
__device__ u16 g_att_lo[(size_t)PB * PS * PD];

// ============================ helpers ======================================
__device__ __forceinline__ uint32_t smem_u32(const void* p) {
    uint32_t a;
    asm("{ .reg .u64 t; cvta.to.shared.u64 t, %1; cvt.u32.u64 %0, t; }"
        : "=r"(a) : "l"(p));
    return a;
}
__device__ __forceinline__ void ldm_x4(uint32_t* r, uint32_t addr) {
    asm volatile("ldmatrix.sync.aligned.m8n8.x4.shared.b16 {%0,%1,%2,%3}, [%4];"
                 : "=r"(r[0]), "=r"(r[1]), "=r"(r[2]), "=r"(r[3]) : "r"(addr));
}
__device__ __forceinline__ void ldm_x4_t(uint32_t* r, uint32_t addr) {
    asm volatile("ldmatrix.sync.aligned.m8n8.x4.trans.shared.b16 {%0,%1,%2,%3}, [%4];"
                 : "=r"(r[0]), "=r"(r[1]), "=r"(r[2]), "=r"(r[3]) : "r"(addr));
}
__device__ __forceinline__ void mma_bf16(float* d, const uint32_t* a, const uint32_t* b) {
    asm volatile(
        "mma.sync.aligned.m16n8k16.row.col.f32.bf16.bf16.f32 "
        "{%0,%1,%2,%3}, {%4,%5,%6,%7}, {%8,%9}, {%0,%1,%2,%3};"
        : "+f"(d[0]), "+f"(d[1]), "+f"(d[2]), "+f"(d[3])
        : "r"(a[0]), "r"(a[1]), "r"(a[2]), "r"(a[3]), "r"(b[0]), "r"(b[1]));
}
__device__ __forceinline__ uint32_t pack2(__nv_bfloat16 x, __nv_bfloat16 y) {
    uint16_t xr = *reinterpret_cast<uint16_t*>(&x);
    uint16_t yr = *reinterpret_cast<uint16_t*>(&y);
    return (uint32_t)xr | ((uint32_t)yr << 16);
}
__device__ __forceinline__ void split4(float4 v, uint2& hi, uint2& lo) {
    __nv_bfloat16 h0 = __float2bfloat16(v.x), h1 = __float2bfloat16(v.y);
    __nv_bfloat16 h2 = __float2bfloat16(v.z), h3 = __float2bfloat16(v.w);
    float r0 = v.x - __bfloat162float(h0);
    float r1 = v.y - __bfloat162float(h1);
    float r2 = v.z - __bfloat162float(h2);
    float r3 = v.w - __bfloat162float(h3);
    hi = make_uint2(pack2(h0, h1), pack2(h2, h3));
    lo = make_uint2(pack2(__float2bfloat16(r0), __float2bfloat16(r1)),
                    pack2(__float2bfloat16(r2), __float2bfloat16(r3)));
}
__device__ __forceinline__ void packhl(float x, float y, uint32_t& hi, uint32_t& lo) {
    __nv_bfloat16 hx = __float2bfloat16(x), hy = __float2bfloat16(y);
    hi = pack2(hx, hy);
    lo = pack2(__float2bfloat16(x - __bfloat162float(hx)),
               __float2bfloat16(y - __bfloat162float(hy)));
}
__device__ __forceinline__ void cp16(uint32_t saddr, const void* gaddr) {
    asm volatile("cp.async.cg.shared.global [%0], [%1], 16;"
                 :: "r"(saddr), "l"(gaddr) : "memory");
}
#define CP_COMMIT() asm volatile("cp.async.commit_group;" ::: "memory")
#define CP_WAIT(n)  asm volatile("cp.async.wait_group %0;" :: "n"(n) : "memory")

// ===================== fp32 -> bf16 hi/lo split ===========================
__global__ void __launch_bounds__(256) split_kernel(
    const float* __restrict__ in, u16* __restrict__ hi, u16* __restrict__ lo)
{
    const size_t i = ((size_t)blockIdx.x * 256 + threadIdx.x) * 4;
    float4 v = *(const float4*)(in + i);
    uint2 h, l;
    split4(v, h, l);
    *(uint2*)&hi[i] = h;
    *(uint2*)&lo[i] = l;
}

// ===================== bf16x3 GEMM, cp.async pipeline =====================
// C = A@B (+bias). A,B preformatted bf16 hi/lo. Block 128x128, K-chunk 32,
// 4-stage cp.async pipeline, 8 warps (4m x 2n), warp tile 32x64.
#define AROW2 80                         // 32 bf16 + 8 pad, bytes
#define BROW2 272                        // 128 bf16 + 8 pad, bytes
#define ATILE2 (128 * AROW2)             // 10240
#define BTILE2 (32 * BROW2)              // 8704
#define STAGE2 (2 * ATILE2 + 2 * BTILE2) // 37888
#define GK2_SMEM (4 * STAGE2)            // 151552

template <bool SPLIT_OUT>
__global__ void __launch_bounds__(256, 1) gemm_pre(
    const u16* __restrict__ Ahi_g, const u16* __restrict__ Alo_g,
    const u16* __restrict__ Bhi_g, const u16* __restrict__ Blo_g,
    const float* __restrict__ bias, float* __restrict__ C,
    u16* __restrict__ Chi, u16* __restrict__ Clo,
    int M, int N, int K)
{
    extern __shared__ char smc[];
    const uint32_t sb = smem_u32(smc);
    const int tid = threadIdx.x, lane = tid & 31, wid = tid >> 5;
    const int row0 = blockIdx.y * 128, col0 = blockIdx.x * 128;
    const int m0 = (wid & 3) * 32, n0 = (wid >> 2) * 64;
    const int g = lane >> 3, lr = lane & 7;

    float acc[2][8][4];
    #pragma unroll
    for (int i = 0; i < 2; i++)
        #pragma unroll
        for (int j = 0; j < 8; j++)
            #pragma unroll
            for (int q = 0; q < 4; q++) acc[i][j][q] = 0.f;

    // issue all cp.asyncs for one K-chunk into stage s
    auto LOADC = [&](int kc, int s) {
        const uint32_t sa = sb + (uint32_t)s * STAGE2;
        #pragma unroll
        for (int it = 0; it < 2; it++) {           // A: 128 rows x 4 16B-chunks
            int e = tid + it * 256;
            int r = e >> 2, c16 = e & 3;
            uint32_t off = sa + r * AROW2 + c16 * 16;
            size_t gi = (size_t)(row0 + r) * K + kc + c16 * 8;
            cp16(off, Ahi_g + gi);
            cp16(off + ATILE2, Alo_g + gi);
        }
        #pragma unroll
        for (int it = 0; it < 2; it++) {           // B: 32 rows x 16 16B-chunks
            int e = tid + it * 256;
            int k = e >> 4, c16 = e & 15;
            uint32_t off = sa + 2 * ATILE2 + k * BROW2 + c16 * 16;
            size_t gi = (size_t)(kc + k) * N + col0 + c16 * 8;
            cp16(off, Bhi_g + gi);
            cp16(off + BTILE2, Blo_g + gi);
        }
        CP_COMMIT();
    };

    auto MMAC = [&](int s) {
        const uint32_t Ah = sb + (uint32_t)s * STAGE2;
        const uint32_t Bh = Ah + 2 * ATILE2;
        #pragma unroll
        for (int ks = 0; ks < 2; ks++) {
            const int kb = ks * 16;
            uint32_t aH[2][4], aL[2][4], bH[8][2], bL[8][2];
            #pragma unroll
            for (int mt = 0; mt < 2; mt++) {
                uint32_t ad = Ah + (m0 + mt * 16 + lr + ((g & 1) << 3)) * AROW2
                                 + (kb + ((g >> 1) << 3)) * 2;
                ldm_x4(aH[mt], ad);
                ldm_x4(aL[mt], ad + ATILE2);
            }
            #pragma unroll
            for (int q = 0; q < 4; q++) {
                int kk = kb + lr + ((g & 1) << 3);
                uint32_t bd = Bh + kk * BROW2 + (n0 + q * 16 + ((g >> 1) << 3)) * 2;
                uint32_t t[4];
                ldm_x4_t(t, bd);
                bH[2 * q][0] = t[0]; bH[2 * q][1] = t[1];
                bH[2 * q + 1][0] = t[2]; bH[2 * q + 1][1] = t[3];
                ldm_x4_t(t, bd + BTILE2);
                bL[2 * q][0] = t[0]; bL[2 * q][1] = t[1];
                bL[2 * q + 1][0] = t[2]; bL[2 * q + 1][1] = t[3];
            }
            #pragma unroll
            for (int mt = 0; mt < 2; mt++)
                #pragma unroll
                for (int nt = 0; nt < 8; nt++) {
                    mma_bf16(acc[mt][nt], aH[mt], bH[nt]);
                    mma_bf16(acc[mt][nt], aH[mt], bL[nt]);
                    mma_bf16(acc[mt][nt], aL[mt], bH[nt]);
                }
        }
    };

    const int NCH = K >> 5;

    LOADC(0, 0);
    LOADC(32, 1);
    LOADC(64, 2);

    for (int c = 0; c < NCH; c++) {
        CP_WAIT(2);
        __syncthreads();
        if (c + 3 < NCH) LOADC((c + 3) << 5, (c + 3) & 3);
        MMAC(c & 3);
    }

    // epilogue
    #pragma unroll
    for (int mt = 0; mt < 2; mt++) {
        #pragma unroll
        for (int nt = 0; nt < 8; nt++) {
            const int r = row0 + m0 + mt * 16 + (lane >> 2);
            const int cc = col0 + n0 + nt * 8 + ((lane & 3) << 1);
            const float b0 = bias[cc], b1 = bias[cc + 1];
            float v00 = acc[mt][nt][0] + b0, v01 = acc[mt][nt][1] + b1;
            float v10 = acc[mt][nt][2] + b0, v11 = acc[mt][nt][3] + b1;
            if (SPLIT_OUT) {
                uint32_t h, l;
                packhl(v00, v01, h, l);
                *(uint32_t*)&Chi[(size_t)r * N + cc] = h;
                *(uint32_t*)&Clo[(size_t)r * N + cc] = l;
                packhl(v10, v11, h, l);
                *(uint32_t*)&Chi[(size_t)(r + 8) * N + cc] = h;
                *(uint32_t*)&Clo[(size_t)(r + 8) * N + cc] = l;
            } else {
                *(float2*)(C + (size_t)r * N + cc) = make_float2(v00, v01);
                *(float2*)(C + (size_t)(r + 8) * N + cc) = make_float2(v10, v11);
            }
        }
    }
}

// ================== Flash attention, bf16x3 mma.sync ======================
// Inputs preformatted bf16 hi/lo; output split to bf16 hi/lo.
#define BQ 128
#define BK 64
#define TROW 272
#define QTILE (128 * TROW)
#define KTILE (64 * TROW)
#define AT_SMEM (2 * QTILE + 4 * KTILE)  // 139264

__global__ void __launch_bounds__(256, 1) attn_mma(
    const u16* __restrict__ qkv_hi, const u16* __restrict__ qkv_lo,
    u16* __restrict__ att_hi, u16* __restrict__ att_lo)
{
    extern __shared__ char smc[];
    const uint32_t sb = smem_u32(smc);
    const uint32_t sQhi = sb;
    const uint32_t sKhi = sb + 2 * QTILE;
    const uint32_t sVhi = sKhi + 2 * KTILE;

    const int qt = (int)gridDim.x - 1 - (int)blockIdx.x;
    const int bh = blockIdx.y;
    const int b  = bh >> 4;
    const int h  = bh & 15;
    const int q0 = qt * BQ;
    const int tid  = threadIdx.x;
    const int lane = tid & 31;
    const int wid  = tid >> 5;
    const int lr   = lane & 7;
    const int g    = lane >> 3;
    const int rl   = lane >> 2;
    const int cq   = (lane & 3) << 1;

    const size_t rs = 3 * PD;
    const size_t base = (size_t)b * PS * rs + (size_t)h * PHD;
    const u16* qh = qkv_hi + base;
    const u16* ql = qkv_lo + base;
    const u16* kh = qh + PD;
    const u16* kl = ql + PD;
    const u16* vh = qh + 2 * PD;
    const u16* vl = ql + 2 * PD;

    // Q tile: 128 rows x 16 16B-chunks, hi + lo
    #pragma unroll
    for (int it = 0; it < 8; it++) {
        int e = tid + it * 256;
        int r = e >> 4, c16 = e & 15;
        uint32_t off = sQhi + r * TROW + c16 * 16;
        size_t gi = (size_t)(q0 + r) * rs + c16 * 8;
        cp16(off, qh + gi);
        cp16(off + QTILE, ql + gi);
    }
    CP_COMMIT();

    float O[16][4];
    #pragma unroll
    for (int nt = 0; nt < 16; nt++)
        #pragma unroll
        for (int c = 0; c < 4; c++) O[nt][c] = 0.f;
    float m0r = -1e30f, m1r = -1e30f, l0r = 0.f, l1r = 0.f;
    const float scale = 0.08838834764831845f;
    const int row_g0 = q0 + wid * 16 + rl;
    const int row_g1 = row_g0 + 8;

    const int nkt = 2 * qt + 2;
    for (int kt = 0; kt < nkt; kt++) {
        const int k0 = kt * BK;
        __syncthreads();   // previous iteration's use of K/V smem complete
        #pragma unroll
        for (int it = 0; it < 4; it++) {           // K,V: 64 rows x 16 chunks
            int e = tid + it * 256;
            int r = e >> 4, c16 = e & 15;
            uint32_t koff = sKhi + r * TROW + c16 * 16;
            uint32_t voff = sVhi + r * TROW + c16 * 16;
            size_t gi = (size_t)(k0 + r) * rs + c16 * 8;
            cp16(koff, kh + gi);
            cp16(koff + KTILE, kl + gi);
            cp16(voff, vh + gi);
            cp16(voff + KTILE, vl + gi);
        }
        CP_COMMIT();
        CP_WAIT(0);
        __syncthreads();

        // ---- S = Q K^T (3-term)
        float S[8][4];
        #pragma unroll
        for (int j = 0; j < 8; j++)
            #pragma unroll
            for (int c = 0; c < 4; c++) S[j][c] = 0.f;

        #pragma unroll
        for (int ks = 0; ks < 8; ks++) {
            uint32_t aH[4], aL[4];
            const uint32_t ad = sQhi + (wid * 16 + lr + ((g & 1) << 3)) * TROW
                                     + (ks * 16 + ((g >> 1) << 3)) * 2;
            ldm_x4(aH, ad);
            ldm_x4(aL, ad + QTILE);
            #pragma unroll
            for (int p = 0; p < 4; p++) {
                uint32_t kH[4], kL[4];
                const uint32_t kd = sKhi + (p * 16 + lr + ((g >> 1) << 3)) * TROW
                                         + (ks * 16 + ((g & 1) << 3)) * 2;
                ldm_x4(kH, kd);
                ldm_x4(kL, kd + KTILE);
                mma_bf16(S[2 * p],     aH, kH);
                mma_bf16(S[2 * p],     aH, kL);
                mma_bf16(S[2 * p],     aL, kH);
                mma_bf16(S[2 * p + 1], aH, kH + 2);
                mma_bf16(S[2 * p + 1], aH, kL + 2);
                mma_bf16(S[2 * p + 1], aL, kH + 2);
            }
        }

        // ---- scale + mask + online softmax
        const bool need_mask = (k0 + BK - 1 > q0);
        float mx0 = -1e30f, mx1 = -1e30f;
        #pragma unroll
        for (int j = 0; j < 8; j++) {
            #pragma unroll
            for (int c = 0; c < 4; c++) {
                float s = S[j][c] * scale;
                if (need_mask) {
                    const int col = k0 + j * 8 + cq + (c & 1);
                    const int row = (c < 2) ? row_g0 : row_g1;
                    if (col > row) s = -1e30f;
                }
                S[j][c] = s;
            }
            mx0 = fmaxf(mx0, fmaxf(S[j][0], S[j][1]));
            mx1 = fmaxf(mx1, fmaxf(S[j][2], S[j][3]));
        }
        #pragma unroll
        for (int off = 1; off <= 2; off <<= 1) {
            mx0 = fmaxf(mx0, __shfl_xor_sync(0xffffffffu, mx0, off));
            mx1 = fmaxf(mx1, __shfl_xor_sync(0xffffffffu, mx1, off));
        }
        const float nm0 = fmaxf(m0r, mx0), nm1 = fmaxf(m1r, mx1);
        const float al0 = __expf(m0r - nm0), al1 = __expf(m1r - nm1);
        float sum0 = 0.f, sum1 = 0.f;
        #pragma unroll
        for (int j = 0; j < 8; j++) {
            S[j][0] = __expf(S[j][0] - nm0);
            S[j][1] = __expf(S[j][1] - nm0);
            S[j][2] = __expf(S[j][2] - nm1);
            S[j][3] = __expf(S[j][3] - nm1);
            sum0 += S[j][0] + S[j][1];
            sum1 += S[j][2] + S[j][3];
        }
        #pragma unroll
        for (int off = 1; off <= 2; off <<= 1) {
            sum0 += __shfl_xor_sync(0xffffffffu, sum0, off);
            sum1 += __shfl_xor_sync(0xffffffffu, sum1, off);
        }
        l0r = l0r * al0 + sum0;
        l1r = l1r * al1 + sum1;
        m0r = nm0; m1r = nm1;
        #pragma unroll
        for (int nt = 0; nt < 16; nt++) {
            O[nt][0] *= al0; O[nt][1] *= al0;
            O[nt][2] *= al1; O[nt][3] *= al1;
        }

        // ---- O += P V (3-term)
        #pragma unroll
        for (int kk = 0; kk < 4; kk++) {
            uint32_t aPh[4], aPl[4];
            const int j0 = 2 * kk, j1 = 2 * kk + 1;
            packhl(S[j0][0], S[j0][1], aPh[0], aPl[0]);
            packhl(S[j0][2], S[j0][3], aPh[1], aPl[1]);
            packhl(S[j1][0], S[j1][1], aPh[2], aPl[2]);
            packhl(S[j1][2], S[j1][3], aPh[3], aPl[3]);
            #pragma unroll
            for (int np = 0; np < 8; np++) {
                uint32_t vH[4], vL[4];
                const uint32_t vd = sVhi + (kk * 16 + lr + ((g & 1) << 3)) * TROW
                                         + (np * 16 + ((g >> 1) << 3)) * 2;
                ldm_x4_t(vH, vd);
                ldm_x4_t(vL, vd + KTILE);
                mma_bf16(O[2 * np],     aPh, vH);
                mma_bf16(O[2 * np],     aPh, vL);
                mma_bf16(O[2 * np],     aPl, vH);
                mma_bf16(O[2 * np + 1], aPh, vH + 2);
                mma_bf16(O[2 * np + 1], aPh, vL + 2);
                mma_bf16(O[2 * np + 1], aPl, vH + 2);
            }
        }
    }

    // ---- normalize + split-write O
    const float inv0 = 1.f / l0r, inv1 = 1.f / l1r;
    const size_t o0 = ((size_t)b * PS + row_g0) * PD + h * PHD;
    const size_t o1 = ((size_t)b * PS + row_g1) * PD + h * PHD;
    #pragma unroll
    for (int nt = 0; nt < 16; nt++) {
        const int col = nt * 8 + cq;
        uint32_t hh, ll;
        packhl(O[nt][0] * inv0, O[nt][1] * inv0, hh, ll);
        *(uint32_t*)&att_hi[o0 + col] = hh;
        *(uint32_t*)&att_lo[o0 + col] = ll;
        packhl(O[nt][2] * inv1, O[nt][3] * inv1, hh, ll);
        *(uint32_t*)&att_hi[o1 + col] = hh;
        *(uint32_t*)&att_lo[o1 + col] = ll;
    }
}

// ---------------------------------------------------------------------------
extern "C" void kernel_launch(void* const* d_in, const int* in_sizes, int n_in,
                              void* d_out, int out_size)
{
    const float* x     = (const float*)d_in[0];
    const float* w_qkv = (const float*)d_in[1];
    const float* b_qkv = (const float*)d_in[2];
    const float* w_out = (const float*)d_in[3];
    const float* b_out = (const float*)d_in[4];
    float* out = (float*)d_out;

    u16 *x_hi, *x_lo, *wq_hi, *wq_lo, *wo_hi, *wo_lo, *qk_hi, *qk_lo, *at_hi, *at_lo;
    cudaGetSymbolAddress((void**)&x_hi,  g_x_hi);
    cudaGetSymbolAddress((void**)&x_lo,  g_x_lo);
    cudaGetSymbolAddress((void**)&wq_hi, g_wqkv_hi);
    cudaGetSymbolAddress((void**)&wq_lo, g_wqkv_lo);
    cudaGetSymbolAddress((void**)&wo_hi, g_wout_hi);
    cudaGetSymbolAddress((void**)&wo_lo, g_wout_lo);
    cudaGetSymbolAddress((void**)&qk_hi, g_qkv_hi);
    cudaGetSymbolAddress((void**)&qk_lo, g_qkv_lo);
    cudaGetSymbolAddress((void**)&at_hi, g_att_hi);
    cudaGetSymbolAddress((void**)&at_lo, g_att_lo);

    cudaFuncSetAttribute(gemm_pre<true>,
                         cudaFuncAttributeMaxDynamicSharedMemorySize, GK2_SMEM);
    cudaFuncSetAttribute(gemm_pre<false>,
                         cudaFuncAttributeMaxDynamicSharedMemorySize, GK2_SMEM);
    cudaFuncSetAttribute(attn_mma,
                         cudaFuncAttributeMaxDynamicSharedMemorySize, AT_SMEM);

    // 1) split inputs to bf16 hi/lo
    split_kernel<<<(PB * PS * PD) / 1024, 256>>>(x, x_hi, x_lo);
    split_kernel<<<(PD * 3 * PD) / 1024, 256>>>(w_qkv, wq_hi, wq_lo);
    split_kernel<<<(PD * PD) / 1024, 256>>>(w_out, wo_hi, wo_lo);

    // 2) QKV projection -> split qkv
    gemm_pre<true><<<dim3(6144 / 128, 4096 / 128), 256, GK2_SMEM>>>(
        x_hi, x_lo, wq_hi, wq_lo, b_qkv, nullptr, qk_hi, qk_lo,
        PB * PS, 3 * PD, PD);
    // 3) attention -> split att
    attn_mma<<<dim3(PS / BQ, PB * PH), 256, AT_SMEM>>>(qk_hi, qk_lo, at_hi, at_lo);
    // 4) output projection -> fp32 out
    gemm_pre<false><<<dim3(2048 / 128, 4096 / 128), 256, GK2_SMEM>>>(
        at_hi, at_lo, wo_hi, wo_lo, b_out, out, nullptr, nullptr,
        PB * PS, PD, PD);
}